// round 2
// baseline (speedup 1.0000x reference)
#include <cuda_runtime.h>
#include <math.h>
#include <stdint.h>

#define VOCABN 128
#define HID    1024
#define BATCHN 256
#define SEQ    256

// ---------------- device scratch (no allocations allowed) ----------------
__device__ float g_P[VOCABN * HID];                      // input-proj LUT, fp32-accurate
__device__ float g_hhi[(size_t)SEQ * BATCHN * HID];      // h_t hi split (tf32-representable)
__device__ float g_hlo[(size_t)SEQ * BATCHN * HID];      // h_t lo split
__device__ float g_whi[HID * HID];                       // Whh splits
__device__ float g_wlo[HID * HID];
__device__ float g_ehi[VOCABN * HID];                    // embed splits (for P)
__device__ float g_elo[VOCABN * HID];
__device__ float g_xwhi[HID * HID];                      // Wxh splits (for P)
__device__ float g_xwlo[HID * HID];
__device__ float g_fchi[VOCABN * HID];                   // fc_w splits
__device__ float g_fclo[VOCABN * HID];

__device__ __forceinline__ uint32_t f2tf(float f) {
    uint32_t u; asm("cvt.rna.tf32.f32 %0, %1;" : "=r"(u) : "f"(f)); return u;
}

__device__ __forceinline__ void mma8(float* c,
                                     uint32_t a0, uint32_t a1, uint32_t a2, uint32_t a3,
                                     uint32_t b0, uint32_t b1) {
    asm volatile(
        "mma.sync.aligned.m16n8k8.row.col.f32.tf32.tf32.f32 "
        "{%0,%1,%2,%3},{%4,%5,%6,%7},{%8,%9},{%0,%1,%2,%3};"
        : "+f"(c[0]), "+f"(c[1]), "+f"(c[2]), "+f"(c[3])
        : "r"(a0), "r"(a1), "r"(a2), "r"(a3), "r"(b0), "r"(b1));
}

// ---------------------------------------------------------------------------
// 3xTF32 GEMM, C[m][n] = epi( sum_{k'} A'[m][k']*B'[n][k'] + bias[n] )
// K' = 3*HID: seg0 = Ahi*Bhi, seg1 = Ahi*Blo, seg2 = Alo*Bhi.
// MODE 0: P precompute      -> C0[m*HID+n] = v
// MODE 1: recurrence step   -> h = tanh(v + P[x[m]][n]); C0/C1 = hi/lo splits of h
// MODE 2: fc projection     -> C0[(b*SEQ+t)*VOCABN+n] = v, rows m = t*BATCHN+b
// Block: 128 thr = 4 warps (2x2), warp tile 16 x (NSUB*8), block tile 32 x (NSUB*16).
// ---------------------------------------------------------------------------
template<int MODE, int NSUB>
__global__ __launch_bounds__(128)
void k_mma(const float* __restrict__ Ahi, const float* __restrict__ Alo,
           const float* __restrict__ Bhi, const float* __restrict__ Blo,
           const float* __restrict__ bias,
           const float* __restrict__ P, const int* __restrict__ x, int tstep,
           float* __restrict__ C0, float* __restrict__ C1)
{
    constexpr int BN  = NSUB * 16;
    constexpr int NB4 = BN / 16;       // float4 B loads per thread per chunk
    constexpr int PAD = 36;            // (36*r + 4g + lt) % 32 == lane -> conflict-free frags

    __shared__ float As[2][32][PAD];
    __shared__ float Bs[2][BN][PAD];

    const int tid  = threadIdx.x;
    const int wid  = tid >> 5, lane = tid & 31;
    const int g    = lane >> 2, lt = lane & 3;
    const int wm0  = (wid >> 1) * 16;
    const int wn0  = (wid & 1) * (NSUB * 8);
    const size_t m0 = (size_t)blockIdx.y * 32;
    const int    n0 = blockIdx.x * BN;

    const float* Aseg[3] = { Ahi, Ahi, Alo };
    const float* Bseg[3] = { Bhi, Blo, Bhi };

    float acc[NSUB][4];
#pragma unroll
    for (int j = 0; j < NSUB; j++)
#pragma unroll
        for (int q = 0; q < 4; q++) acc[j][q] = 0.f;

    // ---- load chunk 0 ----
    {
        const float* Ab = Aseg[0];
        const float* Bb = Bseg[0];
#pragma unroll
        for (int i = 0; i < 2; i++) {
            int id = tid + i * 128, r = id >> 3, k4 = (id & 7) << 2;
            float4 v = *(const float4*)(Ab + (m0 + r) * HID + k4);
            As[0][r][k4 + 0] = v.x; As[0][r][k4 + 1] = v.y;
            As[0][r][k4 + 2] = v.z; As[0][r][k4 + 3] = v.w;
        }
#pragma unroll
        for (int i = 0; i < NB4; i++) {
            int id = tid + i * 128, r = id >> 3, k4 = (id & 7) << 2;
            float4 v = *(const float4*)(Bb + (size_t)(n0 + r) * HID + k4);
            Bs[0][r][k4 + 0] = v.x; Bs[0][r][k4 + 1] = v.y;
            Bs[0][r][k4 + 2] = v.z; Bs[0][r][k4 + 3] = v.w;
        }
    }
    __syncthreads();

    int buf = 0;
    for (int kt = 0; kt < 96; kt++) {                 // 96 chunks of K=32 (3 segs x 32)
        float4 aP[2], bP[NB4];
        if (kt + 1 < 96) {
            int s2  = (kt + 1) >> 5;
            int ko2 = ((kt + 1) & 31) * 32;
            const float* Ab = Aseg[s2];
            const float* Bb = Bseg[s2];
#pragma unroll
            for (int i = 0; i < 2; i++) {
                int id = tid + i * 128, r = id >> 3, k4 = (id & 7) << 2;
                aP[i] = *(const float4*)(Ab + (m0 + r) * HID + ko2 + k4);
            }
#pragma unroll
            for (int i = 0; i < NB4; i++) {
                int id = tid + i * 128, r = id >> 3, k4 = (id & 7) << 2;
                bP[i] = *(const float4*)(Bb + (size_t)(n0 + r) * HID + ko2 + k4);
            }
        }
        // ---- compute 4 k8-steps on current buffer ----
#pragma unroll
        for (int k8 = 0; k8 < 4; k8++) {
            const int ko = k8 * 8;
            uint32_t a0 = __float_as_uint(As[buf][wm0 + g    ][ko + lt    ]);
            uint32_t a1 = __float_as_uint(As[buf][wm0 + g + 8][ko + lt    ]);
            uint32_t a2 = __float_as_uint(As[buf][wm0 + g    ][ko + lt + 4]);
            uint32_t a3 = __float_as_uint(As[buf][wm0 + g + 8][ko + lt + 4]);
#pragma unroll
            for (int j = 0; j < NSUB; j++) {
                uint32_t b0 = __float_as_uint(Bs[buf][wn0 + j * 8 + g][ko + lt    ]);
                uint32_t b1 = __float_as_uint(Bs[buf][wn0 + j * 8 + g][ko + lt + 4]);
                mma8(acc[j], a0, a1, a2, a3, b0, b1);
            }
        }
        // ---- stage prefetch into other buffer ----
        if (kt + 1 < 96) {
#pragma unroll
            for (int i = 0; i < 2; i++) {
                int id = tid + i * 128, r = id >> 3, k4 = (id & 7) << 2;
                As[buf ^ 1][r][k4 + 0] = aP[i].x; As[buf ^ 1][r][k4 + 1] = aP[i].y;
                As[buf ^ 1][r][k4 + 2] = aP[i].z; As[buf ^ 1][r][k4 + 3] = aP[i].w;
            }
#pragma unroll
            for (int i = 0; i < NB4; i++) {
                int id = tid + i * 128, r = id >> 3, k4 = (id & 7) << 2;
                Bs[buf ^ 1][r][k4 + 0] = bP[i].x; Bs[buf ^ 1][r][k4 + 1] = bP[i].y;
                Bs[buf ^ 1][r][k4 + 2] = bP[i].z; Bs[buf ^ 1][r][k4 + 3] = bP[i].w;
            }
        }
        __syncthreads();
        buf ^= 1;
    }

    // ---- epilogue ----
    int xr0 = 0, xr1 = 0;
    if (MODE == 1) {
        xr0 = x[(m0 + wm0 + g    ) * SEQ + tstep];
        xr1 = x[(m0 + wm0 + g + 8) * SEQ + tstep];
    }
#pragma unroll
    for (int j = 0; j < NSUB; j++) {
#pragma unroll
        for (int q = 0; q < 4; q++) {
            size_t m = m0 + wm0 + g + ((q >> 1) ? 8 : 0);
            int    n = n0 + wn0 + j * 8 + lt * 2 + (q & 1);
            float  v = acc[j][q] + bias[n];
            if (MODE == 1) {
                int xr = (q >> 1) ? xr1 : xr0;
                float h = tanhf(v + P[(size_t)xr * HID + n]);
                uint32_t hu = f2tf(h);
                float hf = __uint_as_float(hu);
                C0[m * HID + n] = hf;
                C1[m * HID + n] = __uint_as_float(f2tf(h - hf));
            } else if (MODE == 2) {
                size_t tt = m >> 8;            // BATCHN == 256
                size_t b  = m & 255;
                C0[(b * SEQ + tt) * VOCABN + n] = v;
            } else {
                C0[m * HID + n] = v;
            }
        }
    }
}

// split fp32 -> (tf32 hi, tf32 lo)
__global__ __launch_bounds__(256)
void k_split(const float* __restrict__ w, float* __restrict__ hi,
             float* __restrict__ lo, int n)
{
    int i = blockIdx.x * 256 + threadIdx.x;
    if (i >= n) return;
    float v = w[i];
    uint32_t hu = f2tf(v);
    float hf = __uint_as_float(hu);
    hi[i] = hf;
    lo[i] = __uint_as_float(f2tf(v - hf));
}

// t = 0: h_prev = 0 -> h = tanh(P[x[:,0]] + bhh), emit hi/lo splits
__global__ __launch_bounds__(256)
void k_step0(const int* __restrict__ x, const float* __restrict__ P,
             const float* __restrict__ bias, float* __restrict__ hhi,
             float* __restrict__ hlo)
{
    int idx = blockIdx.x * 256 + threadIdx.x;
    int b = idx >> 10;
    int n = idx & (HID - 1);
    float h = tanhf(P[(size_t)x[b * SEQ] * HID + n] + bias[n]);
    uint32_t hu = f2tf(h);
    float hf = __uint_as_float(hu);
    hhi[idx] = hf;
    hlo[idx] = __uint_as_float(f2tf(h - hf));
}

// hidden output: reconstruct fp32 h from hi+lo (err ~2^-22 rel)
__global__ __launch_bounds__(256)
void k_hidden(const float* __restrict__ hi, const float* __restrict__ lo,
              float* __restrict__ dst)
{
    int i = blockIdx.x * 256 + threadIdx.x;
    dst[i] = hi[i] + lo[i];
}

extern "C" void kernel_launch(void* const* d_in, const int* in_sizes, int n_in,
                              void* d_out, int out_size)
{
    const int*   x     = (const int*)  d_in[0];
    const float* embed = (const float*)d_in[1];
    const float* Wxh_w = (const float*)d_in[2];
    const float* Wxh_b = (const float*)d_in[3];
    const float* Whh_w = (const float*)d_in[4];
    const float* Whh_b = (const float*)d_in[5];
    const float* fc_w  = (const float*)d_in[6];
    const float* fc_b  = (const float*)d_in[7];
    float* outp = (float*)d_out;

    float *P, *hhi, *hlo, *whi, *wlo, *ehi, *elo, *xwhi, *xwlo, *fchi, *fclo;
    cudaGetSymbolAddress((void**)&P,    g_P);
    cudaGetSymbolAddress((void**)&hhi,  g_hhi);
    cudaGetSymbolAddress((void**)&hlo,  g_hlo);
    cudaGetSymbolAddress((void**)&whi,  g_whi);
    cudaGetSymbolAddress((void**)&wlo,  g_wlo);
    cudaGetSymbolAddress((void**)&ehi,  g_ehi);
    cudaGetSymbolAddress((void**)&elo,  g_elo);
    cudaGetSymbolAddress((void**)&xwhi, g_xwhi);
    cudaGetSymbolAddress((void**)&xwlo, g_xwlo);
    cudaGetSymbolAddress((void**)&fchi, g_fchi);
    cudaGetSymbolAddress((void**)&fclo, g_fclo);

    const size_t SLOT = (size_t)BATCHN * HID;

    // 0) weight splits (once per launch)
    k_split<<<(VOCABN * HID) / 256, 256>>>(embed, ehi, elo, VOCABN * HID);
    k_split<<<(HID * HID) / 256, 256>>>(Wxh_w, xwhi, xwlo, HID * HID);
    k_split<<<(HID * HID) / 256, 256>>>(Whh_w, whi, wlo, HID * HID);
    k_split<<<(VOCABN * HID) / 256, 256>>>(fc_w, fchi, fclo, VOCABN * HID);

    // 1) P[v][k] = embed @ Wxh^T + bxh  (3xTF32, error ~2^-24)
    k_mma<0, 4><<<dim3(HID / 64, VOCABN / 32), 128>>>(
        ehi, elo, xwhi, xwlo, Wxh_b, nullptr, nullptr, 0, P, nullptr);

    // 2) t = 0
    k_step0<<<(BATCHN * HID) / 256, 256>>>(x, P, Whh_b, hhi, hlo);

    // 3) recurrence: h_t = tanh(P[x[:,t]] + h_{t-1} @ Whh^T + bhh)
    for (int t = 1; t < SEQ; t++) {
        k_mma<1, 4><<<dim3(HID / 64, BATCHN / 32), 128>>>(
            hhi + (size_t)(t - 1) * SLOT, hlo + (size_t)(t - 1) * SLOT,
            whi, wlo, Whh_b, P, x, t,
            hhi + (size_t)t * SLOT, hlo + (size_t)t * SLOT);
    }

    // 4) fc: out[b][s][v] = h @ fc^T + fc_b   (BN=128 -> h-buffer read once)
    k_mma<2, 8><<<dim3(1, (SEQ * BATCHN) / 32), 128>>>(
        hhi, hlo, fchi, fclo, fc_b, nullptr, nullptr, 0, outp, nullptr);

    // 5) hidden = h_{S-1}
    k_hidden<<<(BATCHN * HID) / 256, 256>>>(
        hhi + (size_t)(SEQ - 1) * SLOT, hlo + (size_t)(SEQ - 1) * SLOT,
        outp + (size_t)BATCHN * SEQ * VOCABN);
}

// round 4
// speedup vs baseline: 3.0906x; 3.0906x over previous
#include <cuda_runtime.h>
#include <cuda_fp16.h>
#include <math.h>
#include <stdint.h>

#define VOCABN 128
#define HID    1024
#define BATCHN 256
#define SEQ    256
#define NSTAGE 4

// ---------------- device scratch (no allocations allowed) ----------------
__device__ float  g_P[VOCABN * HID];                               // input-proj LUT fp32
__device__ __half g_hhi [(size_t)SEQ * BATCHN * HID];              // h hi
__device__ __half g_hhis[(size_t)SEQ * BATCHN * HID];              // h hi / 32
__device__ __half g_hlo [(size_t)SEQ * BATCHN * HID];              // h residual
__device__ __half g_whhhi[HID * HID],  g_whhlos[HID * HID];        // Whh: hi, lo*32
__device__ __half g_wxhhi[HID * HID],  g_wxhlos[HID * HID];        // Wxh: hi, lo*32
__device__ __half g_embhi[VOCABN * HID], g_embhis[VOCABN * HID], g_emblo[VOCABN * HID];
__device__ __half g_fchi[VOCABN * HID],  g_fclos[VOCABN * HID];    // fc_w: hi, lo*32

// ---------------- PTX helpers ----------------
__device__ __forceinline__ uint32_t smem_u32(const void* p) {
    uint32_t a;
    asm("{ .reg .u64 t; cvta.to.shared.u64 t, %1; cvt.u32.u64 %0, t; }" : "=r"(a) : "l"(p));
    return a;
}
#define CP_ASYNC16(dst, src) \
    asm volatile("cp.async.cg.shared.global [%0], [%1], 16;" :: "r"(dst), "l"(src) : "memory")
#define CP_COMMIT() asm volatile("cp.async.commit_group;" ::: "memory")
#define CP_WAIT2()  asm volatile("cp.async.wait_group 2;" ::: "memory")
#define CP_WAIT0()  asm volatile("cp.async.wait_group 0;" ::: "memory")

#define LDSM4(r, addr)                                                            \
    asm volatile("ldmatrix.sync.aligned.m8n8.x4.shared.b16 {%0,%1,%2,%3}, [%4];"  \
        : "=r"((r)[0]), "=r"((r)[1]), "=r"((r)[2]), "=r"((r)[3]) : "r"(addr))

#define MMA16816(c, a, b0, b1)                                                    \
    asm volatile("mma.sync.aligned.m16n8k16.row.col.f32.f16.f16.f32 "             \
        "{%0,%1,%2,%3},{%4,%5,%6,%7},{%8,%9},{%0,%1,%2,%3};"                      \
        : "+f"((c)[0]), "+f"((c)[1]), "+f"((c)[2]), "+f"((c)[3])                   \
        : "r"((a)[0]), "r"((a)[1]), "r"((a)[2]), "r"((a)[3]), "r"(b0), "r"(b1))

// ---------------------------------------------------------------------------
// chunk loader: 1 chunk = K=64 (128 B/row) of A[BM rows] + B[BN rows], SW128.
// K' = 3*1024 in 48 chunks: seg0 = Ahi*Bhi, seg1 = Ahis*Blos, seg2 = Alo*Bhi.
// ---------------------------------------------------------------------------
template<int BM, int BN>
__device__ __forceinline__ void load_chunk(
    uint32_t stg, int tid, int c, size_t m0, int n0,
    const __half* __restrict__ Ahi, const __half* __restrict__ Ahis,
    const __half* __restrict__ Alo,
    const __half* __restrict__ Bhi, const __half* __restrict__ Blos)
{
    const int seg = c >> 4;
    const int k0  = (c & 15) << 6;
    const __half* As = (seg == 0) ? Ahi : ((seg == 1) ? Ahis : Alo);
    const __half* Bs = (seg == 1) ? Blos : Bhi;
#pragma unroll
    for (int i = 0; i < BM * 8 / 256; i++) {
        int id = tid + i * 256, r = id >> 3, cc = id & 7;
        uint32_t off = (uint32_t)(r * 128 + cc * 16);
        off ^= (off >> 3) & 0x70;
        CP_ASYNC16(stg + off, As + (m0 + r) * (size_t)HID + k0 + cc * 8);
    }
#pragma unroll
    for (int i = 0; i < BN * 8 / 256; i++) {
        int id = tid + i * 256, r = id >> 3, cc = id & 7;
        uint32_t off = (uint32_t)(r * 128 + cc * 16);
        off ^= (off >> 3) & 0x70;
        CP_ASYNC16(stg + BM * 128 + off, Bs + (size_t)(n0 + r) * HID + k0 + cc * 8);
    }
    CP_COMMIT();
}

// ---------------------------------------------------------------------------
// 3xFP16 GEMM: C[m][n] = epi( sum_k' A'[m][k'] * B'[n][k'] + bias[n] )
// MODE 0: P precompute (fp32 out). MODE 1: recurrence step
// (tanh(acc+bias+P[x]) -> 3 half splits). MODE 2: fc (permuted fp32 out).
// 256 threads = 8 warps (WM x WN). Warp tile (BM/WM) x (BN/WN).
// ---------------------------------------------------------------------------
template<int MODE, int BM, int BN, int WM, int WN>
__global__ __launch_bounds__(256, 1)
void k_hmma(const __half* __restrict__ Ahi, const __half* __restrict__ Ahis,
            const __half* __restrict__ Alo,
            const __half* __restrict__ Bhi, const __half* __restrict__ Blos,
            const float* __restrict__ bias, const float* __restrict__ P,
            const int* __restrict__ x, int tstep,
            float* __restrict__ Cf, __half* __restrict__ Chi,
            __half* __restrict__ Chis, __half* __restrict__ Clo)
{
    constexpr int TM    = BM / WM;           // warp tile m (mult of 16)
    constexpr int TN    = BN / WN;           // warp tile n (mult of 16)
    constexpr int MF    = TM / 16;
    constexpr int NF2   = TN / 16;           // pairs of n8 fragments
    constexpr int STAGE = (BM + BN) * 128;

    extern __shared__ char smem_raw[];
    const uint32_t sb = (smem_u32(smem_raw) + 1023u) & ~1023u;

    const int tid  = threadIdx.x;
    const int wid  = tid >> 5, lane = tid & 31;
    const int wm   = wid / WN, wn = wid % WN;
    const int n0   = blockIdx.x * BN;
    const size_t m0 = (size_t)blockIdx.y * BM;

    float acc[MF][NF2 * 2][4];
#pragma unroll
    for (int i = 0; i < MF; i++)
#pragma unroll
        for (int j = 0; j < NF2 * 2; j++)
#pragma unroll
            for (int q = 0; q < 4; q++) acc[i][j][q] = 0.f;

    load_chunk<BM, BN>(sb + 0 * STAGE, tid, 0, m0, n0, Ahi, Ahis, Alo, Bhi, Blos);
    load_chunk<BM, BN>(sb + 1 * STAGE, tid, 1, m0, n0, Ahi, Ahis, Alo, Bhi, Blos);
    load_chunk<BM, BN>(sb + 2 * STAGE, tid, 2, m0, n0, Ahi, Ahis, Alo, Bhi, Blos);

#pragma unroll 1
    for (int k = 0; k < 48; k++) {
        CP_WAIT2();                                   // chunk k resident
        __syncthreads();                              // visible to all warps
        if (k + 3 < 48)                               // refill stage (k-1)&3
            load_chunk<BM, BN>(sb + ((k + 3) & 3) * STAGE, tid, k + 3, m0, n0,
                               Ahi, Ahis, Alo, Bhi, Blos);
        const uint32_t stg = sb + (uint32_t)(k & 3) * STAGE;
        const uint32_t aB  = stg;
        const uint32_t bB  = stg + BM * 128;
#pragma unroll
        for (int kk = 0; kk < 4; kk++) {
            uint32_t af[MF][4];
            {
                const int r0 = wm * TM + (lane & 15);
                const int c2 = (kk * 16 + (lane >> 4) * 8) * 2;
#pragma unroll
                for (int mf = 0; mf < MF; mf++) {
                    uint32_t off = (uint32_t)((r0 + mf * 16) * 128 + c2);
                    off ^= (off >> 3) & 0x70;
                    LDSM4(af[mf], aB + off);
                }
            }
            uint32_t bf[NF2][4];
            {
                const int r0 = wn * TN + (lane & 7) + (lane >> 4) * 8;
                const int c2 = (kk * 16 + ((lane >> 3) & 1) * 8) * 2;
#pragma unroll
                for (int np = 0; np < NF2; np++) {
                    uint32_t off = (uint32_t)((r0 + np * 16) * 128 + c2);
                    off ^= (off >> 3) & 0x70;
                    LDSM4(bf[np], bB + off);
                }
            }
#pragma unroll
            for (int mf = 0; mf < MF; mf++)
#pragma unroll
                for (int np = 0; np < NF2; np++) {
                    MMA16816(acc[mf][np * 2],     af[mf], bf[np][0], bf[np][1]);
                    MMA16816(acc[mf][np * 2 + 1], af[mf], bf[np][2], bf[np][3]);
                }
        }
    }

    // ---------------- epilogue ----------------
    const int g = lane >> 2, t4 = lane & 3;
#pragma unroll
    for (int mf = 0; mf < MF; mf++) {
        size_t mrow[2];
        mrow[0] = m0 + wm * TM + mf * 16 + g;
        mrow[1] = mrow[0] + 8;
        const float* Pr[2] = { nullptr, nullptr };
        if (MODE == 1) {
            Pr[0] = P + (size_t)x[mrow[0] * SEQ + tstep] * HID;
            Pr[1] = P + (size_t)x[mrow[1] * SEQ + tstep] * HID;
        }
#pragma unroll
        for (int nf = 0; nf < NF2 * 2; nf++) {
            const int n = n0 + wn * TN + (nf >> 1) * 16 + (nf & 1) * 8 + t4 * 2;
            const float b0 = bias[n], b1 = bias[n + 1];
#pragma unroll
            for (int h2 = 0; h2 < 2; h2++) {
                const size_t m = mrow[h2];
                float v0 = acc[mf][nf][h2 * 2 + 0] + b0;
                float v1 = acc[mf][nf][h2 * 2 + 1] + b1;
                if (MODE == 1) {
                    v0 += Pr[h2][n];
                    v1 += Pr[h2][n + 1];
                    const float h0 = tanhf(v0), h1 = tanhf(v1);
                    const __half hi0 = __float2half_rn(h0);
                    const __half hi1 = __float2half_rn(h1);
                    const float f0 = __half2float(hi0), f1 = __half2float(hi1);
                    *(__half2*)(Chi  + m * HID + n) = __halves2half2(hi0, hi1);
                    *(__half2*)(Chis + m * HID + n) =
                        __halves2half2(__float2half_rn(f0 * 0.03125f),
                                       __float2half_rn(f1 * 0.03125f));
                    *(__half2*)(Clo  + m * HID + n) =
                        __halves2half2(__float2half_rn(h0 - f0),
                                       __float2half_rn(h1 - f1));
                } else if (MODE == 2) {
                    const size_t b = m & 255, tt = m >> 8;
                    float2 o; o.x = v0; o.y = v1;
                    *(float2*)(Cf + (b * SEQ + tt) * VOCABN + n) = o;
                } else {
                    float2 o; o.x = v0; o.y = v1;
                    *(float2*)(Cf + m * HID + n) = o;
                }
            }
        }
    }
}

// ---------------- small kernels ----------------
// weight split: hi = fp16(w), lo_s = fp16((w - hi) * 32)
__global__ __launch_bounds__(256)
void k_split_w(const float* __restrict__ w, __half* __restrict__ hi,
               __half* __restrict__ los, int n)
{
    int i = blockIdx.x * 256 + threadIdx.x;
    if (i >= n) return;
    float v = w[i];
    __half h = __float2half_rn(v);
    hi[i]  = h;
    los[i] = __float2half_rn((v - __half2float(h)) * 32.f);
}

// value split (A side): hi, hi/32, lo
__global__ __launch_bounds__(256)
void k_split_a(const float* __restrict__ w, __half* __restrict__ hi,
               __half* __restrict__ his, __half* __restrict__ lo, int n)
{
    int i = blockIdx.x * 256 + threadIdx.x;
    if (i >= n) return;
    float v = w[i];
    __half h = __float2half_rn(v);
    float f = __half2float(h);
    hi[i]  = h;
    his[i] = __float2half_rn(f * 0.03125f);
    lo[i]  = __float2half_rn(v - f);
}

// t = 0: h = tanh(P[x[:,0]] + bhh) -> 3 splits
__global__ __launch_bounds__(256)
void k_step0(const int* __restrict__ x, const float* __restrict__ P,
             const float* __restrict__ bias, __half* __restrict__ hhi,
             __half* __restrict__ hhis, __half* __restrict__ hlo)
{
    int idx = blockIdx.x * 256 + threadIdx.x;
    int b = idx >> 10, n = idx & (HID - 1);
    float h = tanhf(P[(size_t)x[b * SEQ] * HID + n] + bias[n]);
    __half a = __float2half_rn(h);
    float f = __half2float(a);
    hhi[idx]  = a;
    hhis[idx] = __float2half_rn(f * 0.03125f);
    hlo[idx]  = __float2half_rn(h - f);
}

__global__ __launch_bounds__(256)
void k_hidden(const __half* __restrict__ hi, const __half* __restrict__ lo,
              float* __restrict__ dst)
{
    int i = blockIdx.x * 256 + threadIdx.x;
    dst[i] = __half2float(hi[i]) + __half2float(lo[i]);
}

extern "C" void kernel_launch(void* const* d_in, const int* in_sizes, int n_in,
                              void* d_out, int out_size)
{
    const int*   x     = (const int*)  d_in[0];
    const float* embed = (const float*)d_in[1];
    const float* Wxh_w = (const float*)d_in[2];
    const float* Wxh_b = (const float*)d_in[3];
    const float* Whh_w = (const float*)d_in[4];
    const float* Whh_b = (const float*)d_in[5];
    const float* fc_w  = (const float*)d_in[6];
    const float* fc_b  = (const float*)d_in[7];
    float* outp = (float*)d_out;

    float* P;
    __half *hhi, *hhis, *hlo, *whhhi, *whhlos, *wxhhi, *wxhlos;
    __half *embhi, *embhis, *emblo, *fchi, *fclos;
    cudaGetSymbolAddress((void**)&P,      g_P);
    cudaGetSymbolAddress((void**)&hhi,    g_hhi);
    cudaGetSymbolAddress((void**)&hhis,   g_hhis);
    cudaGetSymbolAddress((void**)&hlo,    g_hlo);
    cudaGetSymbolAddress((void**)&whhhi,  g_whhhi);
    cudaGetSymbolAddress((void**)&whhlos, g_whhlos);
    cudaGetSymbolAddress((void**)&wxhhi,  g_wxhhi);
    cudaGetSymbolAddress((void**)&wxhlos, g_wxhlos);
    cudaGetSymbolAddress((void**)&embhi,  g_embhi);
    cudaGetSymbolAddress((void**)&embhis, g_embhis);
    cudaGetSymbolAddress((void**)&emblo,  g_emblo);
    cudaGetSymbolAddress((void**)&fchi,   g_fchi);
    cudaGetSymbolAddress((void**)&fclos,  g_fclos);

    // smem sizes: (BM+BN)*128*4 + 1024 alignment slack
    const int SM_STEP = (32 + 64)  * 128 * NSTAGE + 1024;   //  50 KB
    const int SM_FC   = (128 + 128) * 128 * NSTAGE + 1024;  // 132 KB
    cudaFuncSetAttribute(k_hmma<0, 32, 64, 2, 4>,
                         cudaFuncAttributeMaxDynamicSharedMemorySize, SM_STEP);
    cudaFuncSetAttribute(k_hmma<1, 32, 64, 2, 4>,
                         cudaFuncAttributeMaxDynamicSharedMemorySize, SM_STEP);
    cudaFuncSetAttribute(k_hmma<2, 128, 128, 4, 2>,
                         cudaFuncAttributeMaxDynamicSharedMemorySize, SM_FC);

    const size_t SLOT = (size_t)BATCHN * HID;

    // 0) operand splits
    k_split_w<<<(HID * HID) / 256, 256>>>(Whh_w, whhhi, whhlos, HID * HID);
    k_split_w<<<(HID * HID) / 256, 256>>>(Wxh_w, wxhhi, wxhlos, HID * HID);
    k_split_w<<<(VOCABN * HID) / 256, 256>>>(fc_w, fchi, fclos, VOCABN * HID);
    k_split_a<<<(VOCABN * HID) / 256, 256>>>(embed, embhi, embhis, emblo, VOCABN * HID);

    // 1) P = embed @ Wxh^T + bxh   (grid 16 x 4 = 64 CTAs)
    k_hmma<0, 32, 64, 2, 4><<<dim3(HID / 64, VOCABN / 32), 256, SM_STEP>>>(
        embhi, embhis, emblo, wxhhi, wxhlos, Wxh_b,
        nullptr, nullptr, 0, P, nullptr, nullptr, nullptr);

    // 2) t = 0
    k_step0<<<(BATCHN * HID) / 256, 256>>>(x, P, Whh_b, hhi, hhis, hlo);

    // 3) recurrence: h_t = tanh(P[x[:,t]] + h_{t-1} @ Whh^T + bhh)   (128 CTAs)
    for (int t = 1; t < SEQ; t++) {
        k_hmma<1, 32, 64, 2, 4><<<dim3(HID / 64, BATCHN / 32), 256, SM_STEP>>>(
            hhi + (size_t)(t - 1) * SLOT, hhis + (size_t)(t - 1) * SLOT,
            hlo + (size_t)(t - 1) * SLOT,
            whhhi, whhlos, Whh_b, P, x, t,
            nullptr, hhi + (size_t)t * SLOT, hhis + (size_t)t * SLOT,
            hlo + (size_t)t * SLOT);
    }

    // 4) fc: out[b][s][v] = h @ fc^T + fc_b   (512 CTAs, A read once/segment)
    k_hmma<2, 128, 128, 4, 2><<<dim3(1, (SEQ * BATCHN) / 128), 256, SM_FC>>>(
        hhi, hhis, hlo, fchi, fclos, fc_b,
        nullptr, nullptr, 0, outp, nullptr, nullptr, nullptr);

    // 5) hidden = h_{S-1}
    k_hidden<<<(BATCHN * HID) / 256, 256>>>(
        hhi + (size_t)(SEQ - 1) * SLOT, hlo + (size_t)(SEQ - 1) * SLOT,
        outp + (size_t)BATCHN * SEQ * VOCABN);
}

// round 5
// speedup vs baseline: 5.1321x; 1.6605x over previous
#include <cuda_runtime.h>
#include <cuda_fp16.h>
#include <math.h>
#include <stdint.h>

#define VOCABN 128
#define HID    1024
#define BATCHN 256
#define SEQ    256
#define NCTA   128

// ---------------- device scratch (no allocations allowed) ----------------
__device__ float    g_P[VOCABN * HID];                        // input-proj LUT fp32
__device__ __half   g_hhi [(size_t)SEQ * BATCHN * HID];       // h hi
__device__ __half   g_hlos[(size_t)SEQ * BATCHN * HID];       // (h - hi) * 32
__device__ __half   g_whhhi[HID * HID], g_whhlos[HID * HID];
__device__ __half   g_wxhhi[HID * HID], g_wxhlos[HID * HID];
__device__ __half   g_embhi[VOCABN * HID], g_emblos[VOCABN * HID];
__device__ __half   g_fchi[VOCABN * HID],  g_fclos[VOCABN * HID];
__device__ unsigned g_bar[SEQ];                               // per-step barrier slots

// ---------------- PTX helpers ----------------
__device__ __forceinline__ uint32_t smem_u32(const void* p) {
    uint32_t a;
    asm("{ .reg .u64 t; cvta.to.shared.u64 t, %1; cvt.u32.u64 %0, t; }" : "=r"(a) : "l"(p));
    return a;
}
__device__ __forceinline__ uint32_t swz(uint32_t o) { return o ^ ((o >> 3) & 0x70); }

#define CP_ASYNC16(dst, src) \
    asm volatile("cp.async.cg.shared.global [%0], [%1], 16;" :: "r"(dst), "l"(src) : "memory")
#define CP_COMMIT() asm volatile("cp.async.commit_group;" ::: "memory")
#define CP_WAIT2()  asm volatile("cp.async.wait_group 2;" ::: "memory")
#define CP_WAIT1()  asm volatile("cp.async.wait_group 1;" ::: "memory")
#define CP_WAIT0()  asm volatile("cp.async.wait_group 0;" ::: "memory")

#define LDSM4(r, addr)                                                            \
    asm volatile("ldmatrix.sync.aligned.m8n8.x4.shared.b16 {%0,%1,%2,%3}, [%4];"  \
        : "=r"((r)[0]), "=r"((r)[1]), "=r"((r)[2]), "=r"((r)[3]) : "r"(addr))

#define MMA16816(c, a, b0, b1)                                                    \
    asm volatile("mma.sync.aligned.m16n8k16.row.col.f32.f16.f16.f32 "             \
        "{%0,%1,%2,%3},{%4,%5,%6,%7},{%8,%9},{%0,%1,%2,%3};"                      \
        : "+f"((c)[0]), "+f"((c)[1]), "+f"((c)[2]), "+f"((c)[3])                   \
        : "r"((a)[0]), "r"((a)[1]), "r"((a)[2]), "r"((a)[3]), "r"(b0), "r"(b1))

// exact wait ladder for 16 chunks, 3 prefetched
__device__ __forceinline__ void wait_chunk(int k0) {
    if (k0 < 14)       CP_WAIT2();
    else if (k0 == 14) CP_WAIT1();
    else               CP_WAIT0();
}

// ===========================================================================
// Persistent recurrence kernel: 128 CTAs, t = 1..255 with grid barrier.
// CTA tile 32(m) x 64(n). Whi slice pinned in smem (128KB); streams
// h_hi, h_los, W_los chunks. acc0 = hi*hi; acc1 = hi*wlos; acc2 = hlos*whi;
// v = acc0 + (acc1+acc2)/32 + bias + P[x]; h = tanh(v) -> hi, (h-hi)*32.
// ===========================================================================
__device__ __forceinline__ void rnn_load_stage(
    uint32_t STG, int tid, int k0,
    const __half* __restrict__ Ahi, const __half* __restrict__ Alo,
    const __half* __restrict__ Wlos, size_t m0, int n0)
{
    const uint32_t stg = STG + (uint32_t)(k0 & 3) * 16384;
    const int r = tid >> 3, cc = tid & 7;
    const int kb = k0 * 64 + cc * 8;
    const uint32_t off = swz((uint32_t)(r * 128 + cc * 16));
    CP_ASYNC16(stg + off,        Ahi + (m0 + r) * (size_t)HID + kb);
    CP_ASYNC16(stg + 4096 + off, Alo + (m0 + r) * (size_t)HID + kb);
    CP_ASYNC16(stg + 8192 + off, Wlos + (size_t)(n0 + r) * HID + kb);
    CP_ASYNC16(stg + 8192 + swz((uint32_t)((r + 32) * 128 + cc * 16)),
               Wlos + (size_t)(n0 + r + 32) * HID + kb);
    CP_COMMIT();
}

__global__ __launch_bounds__(256, 1)
void k_rnn(const __half* __restrict__ Whi, const __half* __restrict__ Wlos,
           const float* __restrict__ bias, const float* __restrict__ P,
           const int* __restrict__ x,
           __half* __restrict__ hhi, __half* __restrict__ hlos)
{
    extern __shared__ char smem_raw[];
    const uint32_t sb  = (smem_u32(smem_raw) + 1023u) & ~1023u;
    const uint32_t PIN = sb;                 // 16 chunks x 8KB = 128KB (Whi slice)
    const uint32_t STG = sb + 131072;        // 4 stages x 16KB

    const int tid = threadIdx.x;
    const int wid = tid >> 5, lane = tid & 31;
    const int wm  = wid >> 2, wn = wid & 3;  // 2 x 4 warps
    const int g   = lane >> 2, t4 = lane & 3;
    const size_t m0 = (size_t)(blockIdx.x >> 4) * 32;
    const int    n0 = (blockIdx.x & 15) * 64;
    const size_t SLOT = (size_t)BATCHN * HID;

    // ---- pin Whi slice ----
    {
        const int r = tid >> 3, cc = tid & 7;
#pragma unroll 1
        for (int k0 = 0; k0 < 16; k0++) {
#pragma unroll
            for (int p = 0; p < 2; p++) {
                int rr = r + p * 32;
                CP_ASYNC16(PIN + k0 * 8192 + swz((uint32_t)(rr * 128 + cc * 16)),
                           Whi + (size_t)(n0 + rr) * HID + k0 * 64 + cc * 8);
            }
        }
        CP_COMMIT(); CP_WAIT0();
    }
    __syncthreads();

    // ---- bias registers (n columns fixed per thread) ----
    float2 bb[2];
#pragma unroll
    for (int nf = 0; nf < 2; nf++) {
        int n = n0 + wn * 16 + nf * 8 + t4 * 2;
        bb[nf].x = bias[n]; bb[nf].y = bias[n + 1];
    }

#pragma unroll 1
    for (int t = 1; t < SEQ; t++) {
        const __half* Ahi = hhi  + (size_t)(t - 1) * SLOT;
        const __half* Alo = hlos + (size_t)(t - 1) * SLOT;
        rnn_load_stage(STG, tid, 0, Ahi, Alo, Wlos, m0, n0);
        rnn_load_stage(STG, tid, 1, Ahi, Alo, Wlos, m0, n0);
        rnn_load_stage(STG, tid, 2, Ahi, Alo, Wlos, m0, n0);

        float acc[3][2][4];
#pragma unroll
        for (int s = 0; s < 3; s++)
#pragma unroll
            for (int j = 0; j < 2; j++)
#pragma unroll
                for (int q = 0; q < 4; q++) acc[s][j][q] = 0.f;

#pragma unroll 1
        for (int k0 = 0; k0 < 16; k0++) {
            wait_chunk(k0);
            __syncthreads();
            if (k0 + 3 < 16)
                rnn_load_stage(STG, tid, k0 + 3, Ahi, Alo, Wlos, m0, n0);
            const uint32_t stg  = STG + (uint32_t)(k0 & 3) * 16384;
            const uint32_t pinc = PIN + (uint32_t)k0 * 8192;
#pragma unroll
            for (int kk = 0; kk < 4; kk++) {
                uint32_t afh[4], afl[4], bfh[4], bfl[4];
                {
                    const int r0 = wm * 16 + (lane & 15);
                    const int c2 = (kk * 16 + (lane >> 4) * 8) * 2;
                    const uint32_t off = swz((uint32_t)(r0 * 128 + c2));
                    LDSM4(afh, stg + off);
                    LDSM4(afl, stg + 4096 + off);
                }
                {
                    const int r0 = wn * 16 + (lane & 7) + ((lane >> 4) << 3);
                    const int c2 = (kk * 16 + ((lane >> 3) & 1) * 8) * 2;
                    const uint32_t off = swz((uint32_t)(r0 * 128 + c2));
                    LDSM4(bfh, pinc + off);
                    LDSM4(bfl, stg + 8192 + off);
                }
                MMA16816(acc[0][0], afh, bfh[0], bfh[1]);
                MMA16816(acc[0][1], afh, bfh[2], bfh[3]);
                MMA16816(acc[1][0], afh, bfl[0], bfl[1]);
                MMA16816(acc[1][1], afh, bfl[2], bfl[3]);
                MMA16816(acc[2][0], afl, bfh[0], bfh[1]);
                MMA16816(acc[2][1], afl, bfh[2], bfh[3]);
            }
        }

        // ---- epilogue ----
        const size_t mr0 = m0 + wm * 16 + g;
        const int xr0 = x[mr0 * SEQ + t];
        const int xr1 = x[(mr0 + 8) * SEQ + t];
        const float* Pr[2] = { P + (size_t)xr0 * HID, P + (size_t)xr1 * HID };
        __half* dhi = hhi  + (size_t)t * SLOT;
        __half* dlo = hlos + (size_t)t * SLOT;
#pragma unroll
        for (int nf = 0; nf < 2; nf++) {
            const int n = n0 + wn * 16 + nf * 8 + t4 * 2;
#pragma unroll
            for (int h2 = 0; h2 < 2; h2++) {
                const size_t m = mr0 + h2 * 8;
                float v0 = acc[0][nf][h2 * 2]     +
                           0.03125f * (acc[1][nf][h2 * 2]     + acc[2][nf][h2 * 2])     +
                           bb[nf].x + Pr[h2][n];
                float v1 = acc[0][nf][h2 * 2 + 1] +
                           0.03125f * (acc[1][nf][h2 * 2 + 1] + acc[2][nf][h2 * 2 + 1]) +
                           bb[nf].y + Pr[h2][n + 1];
                const float h0 = tanhf(v0), h1 = tanhf(v1);
                const __half a0 = __float2half_rn(h0), a1 = __float2half_rn(h1);
                const float f0 = __half2float(a0), f1 = __half2float(a1);
                *(__half2*)(dhi + m * HID + n) = __halves2half2(a0, a1);
                *(__half2*)(dlo + m * HID + n) =
                    __halves2half2(__float2half_rn((h0 - f0) * 32.f),
                                   __float2half_rn((h1 - f1) * 32.f));
            }
        }

        // ---- grid barrier (slot t) ----
        __threadfence();
        __syncthreads();
        if (tid == 0) {
            unsigned* slot = &g_bar[t];
            asm volatile("red.release.gpu.global.add.u32 [%0], %1;"
                         :: "l"(slot), "r"(1u) : "memory");
            unsigned v;
            while (true) {
                asm volatile("ld.acquire.gpu.global.u32 %0, [%1];"
                             : "=r"(v) : "l"(slot) : "memory");
                if (v >= NCTA) break;
                __nanosleep(64);
            }
        }
        __syncthreads();
    }
}

// ===========================================================================
// Generic streaming 3-split GEMM (for P precompute and fc projection).
// acc0 = Ahi*Bhi; acc1 = Ahi*Blos; acc2 = Alos*Bhi; v = acc0+(acc1+acc2)/32+bias
// MODE 0: Cf[m*HID+n] = v.   MODE 2: Cf[(b*SEQ+t)*VOCABN+n] = v (m = t*256+b).
// ===========================================================================
template<int BM, int BN>
__device__ __forceinline__ void g3_load(
    uint32_t STG, int tid, int k0, size_t m0, int n0,
    const __half* __restrict__ Ahi, const __half* __restrict__ Alos,
    const __half* __restrict__ Bhi, const __half* __restrict__ Blos)
{
    constexpr int STAGE = (2 * BM + 2 * BN) * 128;
    const uint32_t stg = STG + (uint32_t)(k0 & 3) * STAGE;
#pragma unroll
    for (int i = 0; i < BM * 8 / 256; i++) {
        int id = tid + i * 256, r = id >> 3, cc = id & 7;
        int kb = k0 * 64 + cc * 8;
        uint32_t off = swz((uint32_t)(r * 128 + cc * 16));
        CP_ASYNC16(stg + off,            Ahi  + (m0 + r) * (size_t)HID + kb);
        CP_ASYNC16(stg + BM * 128 + off, Alos + (m0 + r) * (size_t)HID + kb);
    }
#pragma unroll
    for (int i = 0; i < BN * 8 / 256; i++) {
        int id = tid + i * 256, r = id >> 3, cc = id & 7;
        int kb = k0 * 64 + cc * 8;
        uint32_t off = swz((uint32_t)(r * 128 + cc * 16));
        CP_ASYNC16(stg + 2 * BM * 128 + off,            Bhi  + (size_t)(n0 + r) * HID + kb);
        CP_ASYNC16(stg + 2 * BM * 128 + BN * 128 + off, Blos + (size_t)(n0 + r) * HID + kb);
    }
    CP_COMMIT();
}

template<int MODE, int BM, int BN, int WM, int WN>
__global__ __launch_bounds__(256, 1)
void k_g3(const __half* __restrict__ Ahi, const __half* __restrict__ Alos,
          const __half* __restrict__ Bhi, const __half* __restrict__ Blos,
          const float* __restrict__ bias, float* __restrict__ Cf)
{
    constexpr int TM = BM / WM, TN = BN / WN;
    constexpr int MF = TM / 16, NF2 = TN / 16;
    constexpr int STAGE = (2 * BM + 2 * BN) * 128;

    extern __shared__ char smem_raw[];
    const uint32_t sb = (smem_u32(smem_raw) + 1023u) & ~1023u;
    const int tid = threadIdx.x, wid = tid >> 5, lane = tid & 31;
    const int wm = wid / WN, wn = wid % WN;
    const int n0 = blockIdx.x * BN;
    const size_t m0 = (size_t)blockIdx.y * BM;

    float acc[3][MF][NF2 * 2][4];
#pragma unroll
    for (int s = 0; s < 3; s++)
#pragma unroll
        for (int i = 0; i < MF; i++)
#pragma unroll
            for (int j = 0; j < NF2 * 2; j++)
#pragma unroll
                for (int q = 0; q < 4; q++) acc[s][i][j][q] = 0.f;

    g3_load<BM, BN>(sb, tid, 0, m0, n0, Ahi, Alos, Bhi, Blos);
    g3_load<BM, BN>(sb, tid, 1, m0, n0, Ahi, Alos, Bhi, Blos);
    g3_load<BM, BN>(sb, tid, 2, m0, n0, Ahi, Alos, Bhi, Blos);

#pragma unroll 1
    for (int k0 = 0; k0 < 16; k0++) {
        wait_chunk(k0);
        __syncthreads();
        if (k0 + 3 < 16)
            g3_load<BM, BN>(sb, tid, k0 + 3, m0, n0, Ahi, Alos, Bhi, Blos);
        const uint32_t stg = sb + (uint32_t)(k0 & 3) * STAGE;
        const uint32_t aH = stg, aL = stg + BM * 128;
        const uint32_t bH = stg + 2 * BM * 128, bL = bH + BN * 128;
#pragma unroll
        for (int kk = 0; kk < 4; kk++) {
            uint32_t afh[MF][4], afl[MF][4], bfh[NF2][4], bfl[NF2][4];
            {
                const int r0 = wm * TM + (lane & 15);
                const int c2 = (kk * 16 + (lane >> 4) * 8) * 2;
#pragma unroll
                for (int mf = 0; mf < MF; mf++) {
                    uint32_t off = swz((uint32_t)((r0 + mf * 16) * 128 + c2));
                    LDSM4(afh[mf], aH + off);
                    LDSM4(afl[mf], aL + off);
                }
            }
            {
                const int r0 = wn * TN + (lane & 7) + ((lane >> 4) << 3);
                const int c2 = (kk * 16 + ((lane >> 3) & 1) * 8) * 2;
#pragma unroll
                for (int np = 0; np < NF2; np++) {
                    uint32_t off = swz((uint32_t)((r0 + np * 16) * 128 + c2));
                    LDSM4(bfh[np], bH + off);
                    LDSM4(bfl[np], bL + off);
                }
            }
#pragma unroll
            for (int mf = 0; mf < MF; mf++)
#pragma unroll
                for (int np = 0; np < NF2; np++) {
                    MMA16816(acc[0][mf][np * 2],     afh[mf], bfh[np][0], bfh[np][1]);
                    MMA16816(acc[0][mf][np * 2 + 1], afh[mf], bfh[np][2], bfh[np][3]);
                    MMA16816(acc[1][mf][np * 2],     afh[mf], bfl[np][0], bfl[np][1]);
                    MMA16816(acc[1][mf][np * 2 + 1], afh[mf], bfl[np][2], bfl[np][3]);
                    MMA16816(acc[2][mf][np * 2],     afl[mf], bfh[np][0], bfh[np][1]);
                    MMA16816(acc[2][mf][np * 2 + 1], afl[mf], bfh[np][2], bfh[np][3]);
                }
        }
    }

    // ---- epilogue ----
    const int g = lane >> 2, t4 = lane & 3;
#pragma unroll
    for (int mf = 0; mf < MF; mf++) {
#pragma unroll
        for (int nf = 0; nf < NF2 * 2; nf++) {
            const int n = n0 + wn * TN + (nf >> 1) * 16 + (nf & 1) * 8 + t4 * 2;
            const float b0 = bias[n], b1 = bias[n + 1];
#pragma unroll
            for (int h2 = 0; h2 < 2; h2++) {
                const size_t m = m0 + wm * TM + mf * 16 + g + h2 * 8;
                float2 o;
                o.x = acc[0][mf][nf][h2 * 2] +
                      0.03125f * (acc[1][mf][nf][h2 * 2] + acc[2][mf][nf][h2 * 2]) + b0;
                o.y = acc[0][mf][nf][h2 * 2 + 1] +
                      0.03125f * (acc[1][mf][nf][h2 * 2 + 1] + acc[2][mf][nf][h2 * 2 + 1]) + b1;
                if (MODE == 2) {
                    const size_t b = m & 255, tt = m >> 8;
                    *(float2*)(Cf + (b * SEQ + tt) * VOCABN + n) = o;
                } else {
                    *(float2*)(Cf + m * HID + n) = o;
                }
            }
        }
    }
}

// ---------------- small kernels ----------------
__global__ __launch_bounds__(256)
void k_split(const float* __restrict__ w, __half* __restrict__ hi,
             __half* __restrict__ los, int n)
{
    int i = blockIdx.x * 256 + threadIdx.x;
    if (i >= n) return;
    float v = w[i];
    __half h = __float2half_rn(v);
    hi[i]  = h;
    los[i] = __float2half_rn((v - __half2float(h)) * 32.f);
}

__global__ __launch_bounds__(256)
void k_step0(const int* __restrict__ x, const float* __restrict__ P,
             const float* __restrict__ bias, __half* __restrict__ hhi,
             __half* __restrict__ hlos)
{
    int idx = blockIdx.x * 256 + threadIdx.x;
    int b = idx >> 10, n = idx & (HID - 1);
    float h = tanhf(P[(size_t)x[b * SEQ] * HID + n] + bias[n]);
    __half a = __float2half_rn(h);
    hhi[idx]  = a;
    hlos[idx] = __float2half_rn((h - __half2float(a)) * 32.f);
}

__global__ void k_zero_bar() { g_bar[threadIdx.x] = 0; }

__global__ __launch_bounds__(256)
void k_hidden(const __half* __restrict__ hi, const __half* __restrict__ los,
              float* __restrict__ dst)
{
    int i = blockIdx.x * 256 + threadIdx.x;
    dst[i] = __half2float(hi[i]) + __half2float(los[i]) * 0.03125f;
}

extern "C" void kernel_launch(void* const* d_in, const int* in_sizes, int n_in,
                              void* d_out, int out_size)
{
    const int*   x     = (const int*)  d_in[0];
    const float* embed = (const float*)d_in[1];
    const float* Wxh_w = (const float*)d_in[2];
    const float* Wxh_b = (const float*)d_in[3];
    const float* Whh_w = (const float*)d_in[4];
    const float* Whh_b = (const float*)d_in[5];
    const float* fc_w  = (const float*)d_in[6];
    const float* fc_b  = (const float*)d_in[7];
    float* outp = (float*)d_out;

    float* P;
    __half *hhi, *hlos, *whhhi, *whhlos, *wxhhi, *wxhlos, *embhi, *emblos, *fchi, *fclos;
    cudaGetSymbolAddress((void**)&P,      g_P);
    cudaGetSymbolAddress((void**)&hhi,    g_hhi);
    cudaGetSymbolAddress((void**)&hlos,   g_hlos);
    cudaGetSymbolAddress((void**)&whhhi,  g_whhhi);
    cudaGetSymbolAddress((void**)&whhlos, g_whhlos);
    cudaGetSymbolAddress((void**)&wxhhi,  g_wxhhi);
    cudaGetSymbolAddress((void**)&wxhlos, g_wxhlos);
    cudaGetSymbolAddress((void**)&embhi,  g_embhi);
    cudaGetSymbolAddress((void**)&emblos, g_emblos);
    cudaGetSymbolAddress((void**)&fchi,   g_fchi);
    cudaGetSymbolAddress((void**)&fclos,  g_fclos);

    const int SM_P   = (2 * 32 + 2 * 64) * 128 * 4 + 1024;    //  97 KB
    const int SM_FC  = (2 * 64 + 2 * 128) * 128 * 4 + 1024;   // 193 KB
    const int SM_RNN = 131072 + 4 * 16384 + 1024;             // 193 KB
    cudaFuncSetAttribute(k_g3<0, 32, 64, 2, 4>,
                         cudaFuncAttributeMaxDynamicSharedMemorySize, SM_P);
    cudaFuncSetAttribute(k_g3<2, 64, 128, 2, 4>,
                         cudaFuncAttributeMaxDynamicSharedMemorySize, SM_FC);
    cudaFuncSetAttribute(k_rnn,
                         cudaFuncAttributeMaxDynamicSharedMemorySize, SM_RNN);

    const size_t SLOT = (size_t)BATCHN * HID;

    // 0) operand splits
    k_split<<<(HID * HID) / 256, 256>>>(Whh_w, whhhi, whhlos, HID * HID);
    k_split<<<(HID * HID) / 256, 256>>>(Wxh_w, wxhhi, wxhlos, HID * HID);
    k_split<<<(VOCABN * HID) / 256, 256>>>(fc_w, fchi, fclos, VOCABN * HID);
    k_split<<<(VOCABN * HID) / 256, 256>>>(embed, embhi, emblos, VOCABN * HID);

    // 1) P = embed @ Wxh^T + bxh
    k_g3<0, 32, 64, 2, 4><<<dim3(HID / 64, VOCABN / 32), 256, SM_P>>>(
        embhi, emblos, wxhhi, wxhlos, Wxh_b, P);

    // 2) t = 0
    k_step0<<<(BATCHN * HID) / 256, 256>>>(x, P, Whh_b, hhi, hlos);

    // 3) barrier slots reset, then the persistent recurrence (t = 1..255)
    k_zero_bar<<<1, 256>>>();
    k_rnn<<<NCTA, 256, SM_RNN>>>(whhhi, whhlos, Whh_b, P, x, hhi, hlos);

    // 4) fc: out[b][s][v] = h @ fc^T + fc_b
    k_g3<2, 64, 128, 2, 4><<<dim3(1, (SEQ * BATCHN) / 64), 256, SM_FC>>>(
        hhi, hlos, fchi, fclos, fc_b, outp);

    // 5) hidden = h_{S-1}
    k_hidden<<<(BATCHN * HID) / 256, 256>>>(
        hhi + (size_t)(SEQ - 1) * SLOT, hlos + (size_t)(SEQ - 1) * SLOT,
        outp + (size_t)BATCHN * SEQ * VOCABN);
}

// round 6
// speedup vs baseline: 5.2038x; 1.0140x over previous
#include <cuda_runtime.h>
#include <cuda_fp16.h>
#include <math.h>
#include <stdint.h>

#define VOCABN 128
#define HID    1024
#define BATCHN 256
#define SEQ    256
#define NCTA   128
#define GRPSZ  16u

// ---------------- device scratch (no allocations allowed) ----------------
__device__ float    g_P[VOCABN * HID];                        // input-proj LUT fp32
__device__ __half   g_hhi [(size_t)SEQ * BATCHN * HID];       // h hi
__device__ __half   g_hlos[(size_t)SEQ * BATCHN * HID];       // (h - hi) * 32
__device__ __half   g_whhhi[HID * HID], g_whhlos[HID * HID];
__device__ __half   g_wxhhi[HID * HID], g_wxhlos[HID * HID];
__device__ __half   g_embhi[VOCABN * HID], g_emblos[VOCABN * HID];
__device__ __half   g_fchi[VOCABN * HID],  g_fclos[VOCABN * HID];
__device__ unsigned g_bar[SEQ * 8];                           // per-(step, m-group) slots

// ---------------- PTX helpers ----------------
__device__ __forceinline__ uint32_t smem_u32(const void* p) {
    uint32_t a;
    asm("{ .reg .u64 t; cvta.to.shared.u64 t, %1; cvt.u32.u64 %0, t; }" : "=r"(a) : "l"(p));
    return a;
}
__device__ __forceinline__ uint32_t swz(uint32_t o) { return o ^ ((o >> 3) & 0x70); }

#define CP_ASYNC16(dst, src) \
    asm volatile("cp.async.cg.shared.global [%0], [%1], 16;" :: "r"(dst), "l"(src) : "memory")
#define CP_COMMIT() asm volatile("cp.async.commit_group;" ::: "memory")
#define CP_WAIT2()  asm volatile("cp.async.wait_group 2;" ::: "memory")
#define CP_WAIT1()  asm volatile("cp.async.wait_group 1;" ::: "memory")
#define CP_WAIT0()  asm volatile("cp.async.wait_group 0;" ::: "memory")

#define LDSM4(r, addr)                                                            \
    asm volatile("ldmatrix.sync.aligned.m8n8.x4.shared.b16 {%0,%1,%2,%3}, [%4];"  \
        : "=r"((r)[0]), "=r"((r)[1]), "=r"((r)[2]), "=r"((r)[3]) : "r"(addr))

#define MMA16816(c, a, b0, b1)                                                    \
    asm volatile("mma.sync.aligned.m16n8k16.row.col.f32.f16.f16.f32 "             \
        "{%0,%1,%2,%3},{%4,%5,%6,%7},{%8,%9},{%0,%1,%2,%3};"                      \
        : "+f"((c)[0]), "+f"((c)[1]), "+f"((c)[2]), "+f"((c)[3])                   \
        : "r"((a)[0]), "r"((a)[1]), "r"((a)[2]), "r"((a)[3]), "r"(b0), "r"(b1))

// exact wait ladder: 3 stages in flight (fill may be 6 groups = 3W + 3A,
// in-order retirement makes wait_group 2 equivalent at k0 = 0..2)
__device__ __forceinline__ void wait_chunk(int k0) {
    if (k0 < 14)       CP_WAIT2();
    else if (k0 == 14) CP_WAIT1();
    else               CP_WAIT0();
}

// ===========================================================================
// Persistent recurrence kernel: 128 CTAs, t = 1..255.
// 8 independent m-groups of 16 CTAs; per-(t, grp) barrier.
// CTA tile 32(m) x 64(n). Whi pinned in smem; streams h_hi, h_los, W_los.
// Stage layout (16KB): [A-hi 4KB | A-lo 4KB | Wlos 8KB].
// ===========================================================================
__device__ __forceinline__ void rnn_load_W(
    uint32_t STG, int tid, int k0, const __half* __restrict__ Wlos, int n0)
{
    const uint32_t stg = STG + (uint32_t)(k0 & 3) * 16384;
    const int r = tid >> 3, cc = tid & 7;
    const int kb = k0 * 64 + cc * 8;
    CP_ASYNC16(stg + 8192 + swz((uint32_t)(r * 128 + cc * 16)),
               Wlos + (size_t)(n0 + r) * HID + kb);
    CP_ASYNC16(stg + 8192 + swz((uint32_t)((r + 32) * 128 + cc * 16)),
               Wlos + (size_t)(n0 + r + 32) * HID + kb);
    CP_COMMIT();
}

__device__ __forceinline__ void rnn_load_A(
    uint32_t STG, int tid, int k0,
    const __half* __restrict__ Ahi, const __half* __restrict__ Alo, size_t m0)
{
    const uint32_t stg = STG + (uint32_t)(k0 & 3) * 16384;
    const int r = tid >> 3, cc = tid & 7;
    const int kb = k0 * 64 + cc * 8;
    const uint32_t off = swz((uint32_t)(r * 128 + cc * 16));
    CP_ASYNC16(stg + off,        Ahi + (m0 + r) * (size_t)HID + kb);
    CP_ASYNC16(stg + 4096 + off, Alo + (m0 + r) * (size_t)HID + kb);
    CP_COMMIT();
}

// steady-state refill: W + A of one chunk in a single commit group
__device__ __forceinline__ void rnn_load_stage(
    uint32_t STG, int tid, int k0,
    const __half* __restrict__ Ahi, const __half* __restrict__ Alo,
    const __half* __restrict__ Wlos, size_t m0, int n0)
{
    const uint32_t stg = STG + (uint32_t)(k0 & 3) * 16384;
    const int r = tid >> 3, cc = tid & 7;
    const int kb = k0 * 64 + cc * 8;
    const uint32_t off = swz((uint32_t)(r * 128 + cc * 16));
    CP_ASYNC16(stg + off,        Ahi + (m0 + r) * (size_t)HID + kb);
    CP_ASYNC16(stg + 4096 + off, Alo + (m0 + r) * (size_t)HID + kb);
    CP_ASYNC16(stg + 8192 + off, Wlos + (size_t)(n0 + r) * HID + kb);
    CP_ASYNC16(stg + 8192 + swz((uint32_t)((r + 32) * 128 + cc * 16)),
               Wlos + (size_t)(n0 + r + 32) * HID + kb);
    CP_COMMIT();
}

__global__ __launch_bounds__(256, 1)
void k_rnn(const __half* __restrict__ Whi, const __half* __restrict__ Wlos,
           const float* __restrict__ bias, const float* __restrict__ P,
           const int* __restrict__ x,
           __half* __restrict__ hhi, __half* __restrict__ hlos)
{
    extern __shared__ char smem_raw[];
    const uint32_t sb  = (smem_u32(smem_raw) + 1023u) & ~1023u;
    const uint32_t PIN = sb;                 // 16 chunks x 8KB = 128KB (Whi slice)
    const uint32_t STG = sb + 131072;        // 4 stages x 16KB

    const int tid = threadIdx.x;
    const int wid = tid >> 5, lane = tid & 31;
    const int wm  = wid >> 2, wn = wid & 3;  // 2 x 4 warps
    const int g   = lane >> 2, t4 = lane & 3;
    const int grp = blockIdx.x >> 4;                       // m-group id (0..7)
    const size_t m0 = (size_t)grp * 32;
    const int    n0 = (blockIdx.x & 15) * 64;
    const size_t SLOT = (size_t)BATCHN * HID;

    // ---- pin Whi slice ----
    {
        const int r = tid >> 3, cc = tid & 7;
#pragma unroll 1
        for (int k0 = 0; k0 < 16; k0++) {
#pragma unroll
            for (int p = 0; p < 2; p++) {
                int rr = r + p * 32;
                CP_ASYNC16(PIN + k0 * 8192 + swz((uint32_t)(rr * 128 + cc * 16)),
                           Whi + (size_t)(n0 + rr) * HID + k0 * 64 + cc * 8);
            }
        }
        CP_COMMIT(); CP_WAIT0();
    }
    __syncthreads();

    // ---- bias registers ----
    float2 bb[2];
#pragma unroll
    for (int nf = 0; nf < 2; nf++) {
        int n = n0 + wn * 16 + nf * 8 + t4 * 2;
        bb[nf].x = bias[n]; bb[nf].y = bias[n + 1];
    }

    // W fill for the first step (t-independent)
    rnn_load_W(STG, tid, 0, Wlos, n0);
    rnn_load_W(STG, tid, 1, Wlos, n0);
    rnn_load_W(STG, tid, 2, Wlos, n0);

#pragma unroll 1
    for (int t = 1; t < SEQ; t++) {
        // ---- wait for group (t-1) completion (h_0 comes from k_step0) ----
        if (t > 1) {
            if (tid == 0) {
                const unsigned* slot = &g_bar[(t - 1) * 8 + grp];
                unsigned v;
                while (true) {
                    asm volatile("ld.acquire.gpu.global.u32 %0, [%1];"
                                 : "=r"(v) : "l"(slot) : "memory");
                    if (v >= GRPSZ) break;
                    __nanosleep(32);
                }
            }
            __syncthreads();
        }

        const __half* Ahi = hhi  + (size_t)(t - 1) * SLOT;
        const __half* Alo = hlos + (size_t)(t - 1) * SLOT;
        rnn_load_A(STG, tid, 0, Ahi, Alo, m0);
        rnn_load_A(STG, tid, 1, Ahi, Alo, m0);
        rnn_load_A(STG, tid, 2, Ahi, Alo, m0);

        float acc[3][2][4];
#pragma unroll
        for (int s = 0; s < 3; s++)
#pragma unroll
            for (int j = 0; j < 2; j++)
#pragma unroll
                for (int q = 0; q < 4; q++) acc[s][j][q] = 0.f;

#pragma unroll 1
        for (int k0 = 0; k0 < 16; k0++) {
            wait_chunk(k0);
            __syncthreads();
            if (k0 + 3 < 16)
                rnn_load_stage(STG, tid, k0 + 3, Ahi, Alo, Wlos, m0, n0);
            const uint32_t stg  = STG + (uint32_t)(k0 & 3) * 16384;
            const uint32_t pinc = PIN + (uint32_t)k0 * 8192;
#pragma unroll
            for (int kk = 0; kk < 4; kk++) {
                uint32_t afh[4], afl[4], bfh[4], bfl[4];
                {
                    const int r0 = wm * 16 + (lane & 15);
                    const int c2 = (kk * 16 + (lane >> 4) * 8) * 2;
                    const uint32_t off = swz((uint32_t)(r0 * 128 + c2));
                    LDSM4(afh, stg + off);
                    LDSM4(afl, stg + 4096 + off);
                }
                {
                    const int r0 = wn * 16 + (lane & 7) + ((lane >> 4) << 3);
                    const int c2 = (kk * 16 + ((lane >> 3) & 1) * 8) * 2;
                    const uint32_t off = swz((uint32_t)(r0 * 128 + c2));
                    LDSM4(bfh, pinc + off);
                    LDSM4(bfl, stg + 8192 + off);
                }
                MMA16816(acc[0][0], afh, bfh[0], bfh[1]);
                MMA16816(acc[0][1], afh, bfh[2], bfh[3]);
                MMA16816(acc[1][0], afh, bfl[0], bfl[1]);
                MMA16816(acc[1][1], afh, bfl[2], bfl[3]);
                MMA16816(acc[2][0], afl, bfh[0], bfh[1]);
                MMA16816(acc[2][1], afl, bfh[2], bfh[3]);
            }
        }

        // ---- W fill for next step: overlaps epilogue + barrier ----
        if (t + 1 < SEQ) {
            rnn_load_W(STG, tid, 0, Wlos, n0);
            rnn_load_W(STG, tid, 1, Wlos, n0);
            rnn_load_W(STG, tid, 2, Wlos, n0);
        }

        // ---- epilogue ----
        const size_t mr0 = m0 + wm * 16 + g;
        const int xr0 = x[mr0 * SEQ + t];
        const int xr1 = x[(mr0 + 8) * SEQ + t];
        const float* Pr[2] = { P + (size_t)xr0 * HID, P + (size_t)xr1 * HID };
        __half* dhi = hhi  + (size_t)t * SLOT;
        __half* dlo = hlos + (size_t)t * SLOT;
#pragma unroll
        for (int nf = 0; nf < 2; nf++) {
            const int n = n0 + wn * 16 + nf * 8 + t4 * 2;
#pragma unroll
            for (int h2 = 0; h2 < 2; h2++) {
                const size_t m = mr0 + h2 * 8;
                float v0 = acc[0][nf][h2 * 2]     +
                           0.03125f * (acc[1][nf][h2 * 2]     + acc[2][nf][h2 * 2])     +
                           bb[nf].x + Pr[h2][n];
                float v1 = acc[0][nf][h2 * 2 + 1] +
                           0.03125f * (acc[1][nf][h2 * 2 + 1] + acc[2][nf][h2 * 2 + 1]) +
                           bb[nf].y + Pr[h2][n + 1];
                const float h0 = tanhf(v0), h1 = tanhf(v1);
                const __half a0 = __float2half_rn(h0), a1 = __float2half_rn(h1);
                const float f0 = __half2float(a0), f1 = __half2float(a1);
                *(__half2*)(dhi + m * HID + n) = __halves2half2(a0, a1);
                *(__half2*)(dlo + m * HID + n) =
                    __halves2half2(__float2half_rn((h0 - f0) * 32.f),
                                   __float2half_rn((h1 - f1) * 32.f));
            }
        }

        // ---- group arrive (slot (t, grp)) ----
        __threadfence();
        __syncthreads();
        if (tid == 0) {
            unsigned* slot = &g_bar[t * 8 + grp];
            asm volatile("red.release.gpu.global.add.u32 [%0], %1;"
                         :: "l"(slot), "r"(1u) : "memory");
        }
    }
}

// ===========================================================================
// Generic streaming 3-split GEMM (P precompute, fc projection). Unchanged.
// ===========================================================================
template<int BM, int BN>
__device__ __forceinline__ void g3_load(
    uint32_t STG, int tid, int k0, size_t m0, int n0,
    const __half* __restrict__ Ahi, const __half* __restrict__ Alos,
    const __half* __restrict__ Bhi, const __half* __restrict__ Blos)
{
    constexpr int STAGE = (2 * BM + 2 * BN) * 128;
    const uint32_t stg = STG + (uint32_t)(k0 & 3) * STAGE;
#pragma unroll
    for (int i = 0; i < BM * 8 / 256; i++) {
        int id = tid + i * 256, r = id >> 3, cc = id & 7;
        int kb = k0 * 64 + cc * 8;
        uint32_t off = swz((uint32_t)(r * 128 + cc * 16));
        CP_ASYNC16(stg + off,            Ahi  + (m0 + r) * (size_t)HID + kb);
        CP_ASYNC16(stg + BM * 128 + off, Alos + (m0 + r) * (size_t)HID + kb);
    }
#pragma unroll
    for (int i = 0; i < BN * 8 / 256; i++) {
        int id = tid + i * 256, r = id >> 3, cc = id & 7;
        int kb = k0 * 64 + cc * 8;
        uint32_t off = swz((uint32_t)(r * 128 + cc * 16));
        CP_ASYNC16(stg + 2 * BM * 128 + off,            Bhi  + (size_t)(n0 + r) * HID + kb);
        CP_ASYNC16(stg + 2 * BM * 128 + BN * 128 + off, Blos + (size_t)(n0 + r) * HID + kb);
    }
    CP_COMMIT();
}

template<int MODE, int BM, int BN, int WM, int WN>
__global__ __launch_bounds__(256, 1)
void k_g3(const __half* __restrict__ Ahi, const __half* __restrict__ Alos,
          const __half* __restrict__ Bhi, const __half* __restrict__ Blos,
          const float* __restrict__ bias, float* __restrict__ Cf)
{
    constexpr int TM = BM / WM, TN = BN / WN;
    constexpr int MF = TM / 16, NF2 = TN / 16;
    constexpr int STAGE = (2 * BM + 2 * BN) * 128;

    extern __shared__ char smem_raw[];
    const uint32_t sb = (smem_u32(smem_raw) + 1023u) & ~1023u;
    const int tid = threadIdx.x, wid = tid >> 5, lane = tid & 31;
    const int wm = wid / WN, wn = wid % WN;
    const int n0 = blockIdx.x * BN;
    const size_t m0 = (size_t)blockIdx.y * BM;

    float acc[3][MF][NF2 * 2][4];
#pragma unroll
    for (int s = 0; s < 3; s++)
#pragma unroll
        for (int i = 0; i < MF; i++)
#pragma unroll
            for (int j = 0; j < NF2 * 2; j++)
#pragma unroll
                for (int q = 0; q < 4; q++) acc[s][i][j][q] = 0.f;

    g3_load<BM, BN>(sb, tid, 0, m0, n0, Ahi, Alos, Bhi, Blos);
    g3_load<BM, BN>(sb, tid, 1, m0, n0, Ahi, Alos, Bhi, Blos);
    g3_load<BM, BN>(sb, tid, 2, m0, n0, Ahi, Alos, Bhi, Blos);

#pragma unroll 1
    for (int k0 = 0; k0 < 16; k0++) {
        wait_chunk(k0);
        __syncthreads();
        if (k0 + 3 < 16)
            g3_load<BM, BN>(sb, tid, k0 + 3, m0, n0, Ahi, Alos, Bhi, Blos);
        const uint32_t stg = sb + (uint32_t)(k0 & 3) * STAGE;
        const uint32_t aH = stg, aL = stg + BM * 128;
        const uint32_t bH = stg + 2 * BM * 128, bL = bH + BN * 128;
#pragma unroll
        for (int kk = 0; kk < 4; kk++) {
            uint32_t afh[MF][4], afl[MF][4], bfh[NF2][4], bfl[NF2][4];
            {
                const int r0 = wm * TM + (lane & 15);
                const int c2 = (kk * 16 + (lane >> 4) * 8) * 2;
#pragma unroll
                for (int mf = 0; mf < MF; mf++) {
                    uint32_t off = swz((uint32_t)((r0 + mf * 16) * 128 + c2));
                    LDSM4(afh[mf], aH + off);
                    LDSM4(afl[mf], aL + off);
                }
            }
            {
                const int r0 = wn * TN + (lane & 7) + ((lane >> 4) << 3);
                const int c2 = (kk * 16 + ((lane >> 3) & 1) * 8) * 2;
#pragma unroll
                for (int np = 0; np < NF2; np++) {
                    uint32_t off = swz((uint32_t)((r0 + np * 16) * 128 + c2));
                    LDSM4(bfh[np], bH + off);
                    LDSM4(bfl[np], bL + off);
                }
            }
#pragma unroll
            for (int mf = 0; mf < MF; mf++)
#pragma unroll
                for (int np = 0; np < NF2; np++) {
                    MMA16816(acc[0][mf][np * 2],     afh[mf], bfh[np][0], bfh[np][1]);
                    MMA16816(acc[0][mf][np * 2 + 1], afh[mf], bfh[np][2], bfh[np][3]);
                    MMA16816(acc[1][mf][np * 2],     afh[mf], bfl[np][0], bfl[np][1]);
                    MMA16816(acc[1][mf][np * 2 + 1], afh[mf], bfl[np][2], bfl[np][3]);
                    MMA16816(acc[2][mf][np * 2],     afl[mf], bfh[np][0], bfh[np][1]);
                    MMA16816(acc[2][mf][np * 2 + 1], afl[mf], bfh[np][2], bfh[np][3]);
                }
        }
    }

    const int g = lane >> 2, t4 = lane & 3;
#pragma unroll
    for (int mf = 0; mf < MF; mf++) {
#pragma unroll
        for (int nf = 0; nf < NF2 * 2; nf++) {
            const int n = n0 + wn * TN + (nf >> 1) * 16 + (nf & 1) * 8 + t4 * 2;
            const float b0 = bias[n], b1 = bias[n + 1];
#pragma unroll
            for (int h2 = 0; h2 < 2; h2++) {
                const size_t m = m0 + wm * TM + mf * 16 + g + h2 * 8;
                float2 o;
                o.x = acc[0][mf][nf][h2 * 2] +
                      0.03125f * (acc[1][mf][nf][h2 * 2] + acc[2][mf][nf][h2 * 2]) + b0;
                o.y = acc[0][mf][nf][h2 * 2 + 1] +
                      0.03125f * (acc[1][mf][nf][h2 * 2 + 1] + acc[2][mf][nf][h2 * 2 + 1]) + b1;
                if (MODE == 2) {
                    const size_t b = m & 255, tt = m >> 8;
                    *(float2*)(Cf + (b * SEQ + tt) * VOCABN + n) = o;
                } else {
                    *(float2*)(Cf + m * HID + n) = o;
                }
            }
        }
    }
}

// ---------------- small kernels ----------------
__global__ __launch_bounds__(256)
void k_split(const float* __restrict__ w, __half* __restrict__ hi,
             __half* __restrict__ los, int n)
{
    int i = blockIdx.x * 256 + threadIdx.x;
    if (i >= n) return;
    float v = w[i];
    __half h = __float2half_rn(v);
    hi[i]  = h;
    los[i] = __float2half_rn((v - __half2float(h)) * 32.f);
}

__global__ __launch_bounds__(256)
void k_step0(const int* __restrict__ x, const float* __restrict__ P,
             const float* __restrict__ bias, __half* __restrict__ hhi,
             __half* __restrict__ hlos)
{
    int idx = blockIdx.x * 256 + threadIdx.x;
    int b = idx >> 10, n = idx & (HID - 1);
    float h = tanhf(P[(size_t)x[b * SEQ] * HID + n] + bias[n]);
    __half a = __float2half_rn(h);
    hhi[idx]  = a;
    hlos[idx] = __float2half_rn((h - __half2float(a)) * 32.f);
}

__global__ void k_zero_bar() { g_bar[blockIdx.x * 256 + threadIdx.x] = 0; }

__global__ __launch_bounds__(256)
void k_hidden(const __half* __restrict__ hi, const __half* __restrict__ los,
              float* __restrict__ dst)
{
    int i = blockIdx.x * 256 + threadIdx.x;
    dst[i] = __half2float(hi[i]) + __half2float(los[i]) * 0.03125f;
}

extern "C" void kernel_launch(void* const* d_in, const int* in_sizes, int n_in,
                              void* d_out, int out_size)
{
    const int*   x     = (const int*)  d_in[0];
    const float* embed = (const float*)d_in[1];
    const float* Wxh_w = (const float*)d_in[2];
    const float* Wxh_b = (const float*)d_in[3];
    const float* Whh_w = (const float*)d_in[4];
    const float* Whh_b = (const float*)d_in[5];
    const float* fc_w  = (const float*)d_in[6];
    const float* fc_b  = (const float*)d_in[7];
    float* outp = (float*)d_out;

    float* P;
    __half *hhi, *hlos, *whhhi, *whhlos, *wxhhi, *wxhlos, *embhi, *emblos, *fchi, *fclos;
    cudaGetSymbolAddress((void**)&P,      g_P);
    cudaGetSymbolAddress((void**)&hhi,    g_hhi);
    cudaGetSymbolAddress((void**)&hlos,   g_hlos);
    cudaGetSymbolAddress((void**)&whhhi,  g_whhhi);
    cudaGetSymbolAddress((void**)&whhlos, g_whhlos);
    cudaGetSymbolAddress((void**)&wxhhi,  g_wxhhi);
    cudaGetSymbolAddress((void**)&wxhlos, g_wxhlos);
    cudaGetSymbolAddress((void**)&embhi,  g_embhi);
    cudaGetSymbolAddress((void**)&emblos, g_emblos);
    cudaGetSymbolAddress((void**)&fchi,   g_fchi);
    cudaGetSymbolAddress((void**)&fclos,  g_fclos);

    const int SM_P   = (2 * 32 + 2 * 64) * 128 * 4 + 1024;    //  97 KB
    const int SM_FC  = (2 * 64 + 2 * 128) * 128 * 4 + 1024;   // 193 KB
    const int SM_RNN = 131072 + 4 * 16384 + 1024;             // 193 KB
    cudaFuncSetAttribute(k_g3<0, 32, 64, 2, 4>,
                         cudaFuncAttributeMaxDynamicSharedMemorySize, SM_P);
    cudaFuncSetAttribute(k_g3<2, 64, 128, 2, 4>,
                         cudaFuncAttributeMaxDynamicSharedMemorySize, SM_FC);
    cudaFuncSetAttribute(k_rnn,
                         cudaFuncAttributeMaxDynamicSharedMemorySize, SM_RNN);

    const size_t SLOT = (size_t)BATCHN * HID;

    // 0) operand splits
    k_split<<<(HID * HID) / 256, 256>>>(Whh_w, whhhi, whhlos, HID * HID);
    k_split<<<(HID * HID) / 256, 256>>>(Wxh_w, wxhhi, wxhlos, HID * HID);
    k_split<<<(VOCABN * HID) / 256, 256>>>(fc_w, fchi, fclos, VOCABN * HID);
    k_split<<<(VOCABN * HID) / 256, 256>>>(embed, embhi, emblos, VOCABN * HID);

    // 1) P = embed @ Wxh^T + bxh
    k_g3<0, 32, 64, 2, 4><<<dim3(HID / 64, VOCABN / 32), 256, SM_P>>>(
        embhi, emblos, wxhhi, wxhlos, Wxh_b, P);

    // 2) t = 0
    k_step0<<<(BATCHN * HID) / 256, 256>>>(x, P, Whh_b, hhi, hlos);

    // 3) reset barrier slots, then the persistent recurrence (t = 1..255)
    k_zero_bar<<<8, 256>>>();
    k_rnn<<<NCTA, 256, SM_RNN>>>(whhhi, whhlos, Whh_b, P, x, hhi, hlos);

    // 4) fc: out[b][s][v] = h @ fc^T + fc_b
    k_g3<2, 64, 128, 2, 4><<<dim3(1, (SEQ * BATCHN) / 64), 256, SM_FC>>>(
        hhi, hlos, fchi, fclos, fc_b, outp);

    // 5) hidden = h_{S-1}
    k_hidden<<<(BATCHN * HID) / 256, 256>>>(
        hhi + (size_t)(SEQ - 1) * SLOT, hlos + (size_t)(SEQ - 1) * SLOT,
        outp + (size_t)BATCHN * SEQ * VOCABN);
}